// round 2
// baseline (speedup 1.0000x reference)
#include <cuda_runtime.h>
#include <math.h>

// ---------------- problem dims ----------------
#define B_ROWS 16384
#define D_VIS  1024
#define D_H    256
#define E_NUM  4
#define G_NUM  5000
#define MAP_   128
#define SCVI_  30
#define N_GD2  (G_NUM*2)

// ---------------- GEMM tile config ----------------
#define BM 128
#define BN 128
#define BK 16
#define TM 8
#define TN 8
#define NTHREADS 256
#define AS_LD (BM+4)
#define MAX_TILES 132   // upper bound on padded row tiles for MoE grouping

// ---------------- scratch (static device globals; no allocation allowed) ----------------
__device__ float g_four[(size_t)B_ROWS*2*MAP_];     // [B,256]
__device__ float g_z   [(size_t)B_ROWS*D_H];        // encoder output z
__device__ float g_zf  [(size_t)B_ROWS*D_H];        // z + moe
__device__ float g_tpre[(size_t)B_ROWS*D_H];        // pre-LN
__device__ float g_t   [(size_t)B_ROWS*D_H];        // post LN+gelu
__device__ float g_a1  [(size_t)B_ROWS*128];        // align hidden
__device__ float g_f1  [(size_t)B_ROWS*64];         // func hidden
__device__ float g_h   [(size_t)MAX_TILES*BM*1024]; // MoE hidden (slot-major)
__device__ int   g_eid [B_ROWS];
__device__ float g_gate[B_ROWS];
__device__ int   g_perm[MAX_TILES*BM];
__device__ int   g_counts[E_NUM];
__device__ int   g_cursor[E_NUM];
__device__ int   g_padoff[E_NUM+1];

// ---------------- helpers ----------------
__device__ __forceinline__ float gelu_exact(float x) {
    return 0.5f * x * (1.0f + erff(x * 0.70710678118654752440f));
}

// Core tiled GEMM accumulate: acc += A[m0..m0+127, 0..K) * W[0..K, n0..n0+127)
// A is [.,lda] row-major; W is [K,N] row-major. If perm != nullptr, A row for
// tile row r is perm[m0+r] (negative -> zero row).
__device__ __forceinline__ void gemm_accum(
    float acc[TM][TN],
    const float* __restrict__ A, int lda, int K,
    const float* __restrict__ W, int N,
    int m0, int n0,
    const int* __restrict__ perm,
    float* As, float* Bs)
{
    const int tid = threadIdx.x;
    const int aR = tid >> 2;          // 0..63
    const int aC = (tid & 3) * 4;     // 0,4,8,12
    const int bR = tid >> 5;          // 0..7
    const int bC = (tid & 31) * 4;    // 0..124
    const bool nguard = (n0 + BN > N);
    const int trow = tid >> 4;        // 0..15
    const int tcol = tid & 15;        // 0..15

    int row0, row1;
    if (perm) { row0 = perm[m0 + aR]; row1 = perm[m0 + aR + 64]; }
    else      { row0 = m0 + aR;       row1 = m0 + aR + 64; }

    for (int k0 = 0; k0 < K; k0 += BK) {
        float4 va0 = make_float4(0.f,0.f,0.f,0.f);
        float4 va1 = make_float4(0.f,0.f,0.f,0.f);
        if (row0 >= 0) va0 = *(const float4*)(A + (size_t)row0 * lda + k0 + aC);
        if (row1 >= 0) va1 = *(const float4*)(A + (size_t)row1 * lda + k0 + aC);
        As[(aC+0)*AS_LD + aR]      = va0.x;
        As[(aC+1)*AS_LD + aR]      = va0.y;
        As[(aC+2)*AS_LD + aR]      = va0.z;
        As[(aC+3)*AS_LD + aR]      = va0.w;
        As[(aC+0)*AS_LD + aR + 64] = va1.x;
        As[(aC+1)*AS_LD + aR + 64] = va1.y;
        As[(aC+2)*AS_LD + aR + 64] = va1.z;
        As[(aC+3)*AS_LD + aR + 64] = va1.w;

        if (!nguard) {
            *(float4*)&Bs[bR*BN + bC]     = *(const float4*)(W + (size_t)(k0+bR)  *N + n0 + bC);
            *(float4*)&Bs[(bR+8)*BN + bC] = *(const float4*)(W + (size_t)(k0+bR+8)*N + n0 + bC);
        } else {
            #pragma unroll
            for (int j = 0; j < 4; j++) {
                int n = n0 + bC + j;
                Bs[bR*BN + bC + j]     = (n < N) ? W[(size_t)(k0+bR)  *N + n] : 0.f;
                Bs[(bR+8)*BN + bC + j] = (n < N) ? W[(size_t)(k0+bR+8)*N + n] : 0.f;
            }
        }
        __syncthreads();

        #pragma unroll
        for (int k = 0; k < BK; k++) {
            float a[TM], b[TN];
            *(float4*)&a[0] = *(float4*)&As[k*AS_LD + trow*TM];
            *(float4*)&a[4] = *(float4*)&As[k*AS_LD + trow*TM + 4];
            *(float4*)&b[0] = *(float4*)&Bs[k*BN + tcol*TN];
            *(float4*)&b[4] = *(float4*)&Bs[k*BN + tcol*TN + 4];
            #pragma unroll
            for (int i = 0; i < TM; i++)
                #pragma unroll
                for (int j = 0; j < TN; j++)
                    acc[i][j] = fmaf(a[i], b[j], acc[i][j]);
        }
        __syncthreads();
    }
}

#define GEMM_SMEM \
    __shared__ __align__(16) float As[BK*AS_LD]; \
    __shared__ __align__(16) float Bs[BK*BN];

// ---------------- stage kernels ----------------

// Fourier features: four = [sin(2pi*pos@fB), cos(2pi*pos@fB)]
__global__ void k_four(const float* __restrict__ pos, const float* __restrict__ fB) {
    int warp = threadIdx.x >> 5, lane = threadIdx.x & 31;
    int row = blockIdx.x * 8 + warp;
    float p0 = pos[row*3+0], p1 = pos[row*3+1], p2 = pos[row*3+2];
    #pragma unroll
    for (int i = 0; i < 4; i++) {
        int c = lane + 32*i;
        float xp = 6.283185307179586477f * (p0*fB[c] + p1*fB[MAP_+c] + p2*fB[2*MAP_+c]);
        float s, co;
        sincosf(xp, &s, &co);
        g_four[(size_t)row*256 + c]       = s;
        g_four[(size_t)row*256 + 128 + c] = co;
    }
}

// z = vis@img_W + img_b + gelu(four@pos_W + pos_b)
__global__ void k_gemm_z(const float* __restrict__ vis,
                         const float* __restrict__ img_W, const float* __restrict__ img_b,
                         const float* __restrict__ pos_W, const float* __restrict__ pos_b) {
    GEMM_SMEM
    float acc[TM][TN] = {};
    int m0 = blockIdx.y * BM, n0 = blockIdx.x * BN;
    int trow = threadIdx.x >> 4, tcol = threadIdx.x & 15;

    gemm_accum(acc, g_four, 256, 256, pos_W, 256, m0, n0, nullptr, As, Bs);
    #pragma unroll
    for (int i = 0; i < TM; i++)
        #pragma unroll
        for (int j = 0; j < TN; j++) {
            int col = n0 + tcol*TN + j;
            acc[i][j] = gelu_exact(acc[i][j] + pos_b[col]);
        }
    gemm_accum(acc, vis, D_VIS, D_VIS, img_W, 256, m0, n0, nullptr, As, Bs);
    #pragma unroll
    for (int i = 0; i < TM; i++)
        #pragma unroll
        for (int j = 0; j < TN; j++) {
            int row = m0 + trow*TM + i, col = n0 + tcol*TN + j;
            g_z[(size_t)row*256 + col] = acc[i][j] + img_b[col];
        }
}

__global__ void k_init() {
    int idx = blockIdx.x * blockDim.x + threadIdx.x;
    if (idx < MAX_TILES*BM) g_perm[idx] = -1;
    if (idx < E_NUM) { g_counts[idx] = 0; g_cursor[idx] = 0; }
}

// router: logits[4] -> softmax -> (argmax first-max, gate = max prob)
__global__ void k_router(const float* __restrict__ grad,
                         const float* __restrict__ rW, const float* __restrict__ rb) {
    int warp = threadIdx.x >> 5, lane = threadIdx.x & 31;
    int row = blockIdx.x * 8 + warp;
    float4 s = make_float4(0.f,0.f,0.f,0.f);
    #pragma unroll
    for (int i = 0; i < 8; i++) {
        int k = lane + 32*i;
        float zv = g_z[(size_t)row*256 + k];
        float4 w = *(const float4*)(rW + k*4);
        s.x = fmaf(zv, w.x, s.x);
        s.y = fmaf(zv, w.y, s.y);
        s.z = fmaf(zv, w.z, s.z);
        s.w = fmaf(zv, w.w, s.w);
    }
    #pragma unroll
    for (int off = 16; off; off >>= 1) {
        s.x += __shfl_down_sync(0xffffffffu, s.x, off);
        s.y += __shfl_down_sync(0xffffffffu, s.y, off);
        s.z += __shfl_down_sync(0xffffffffu, s.z, off);
        s.w += __shfl_down_sync(0xffffffffu, s.w, off);
    }
    if (lane == 0) {
        float gv = grad[row];
        float4 wg = *(const float4*)(rW + 256*4);
        float l0 = s.x + gv*wg.x + rb[0];
        float l1 = s.y + gv*wg.y + rb[1];
        float l2 = s.z + gv*wg.z + rb[2];
        float l3 = s.w + gv*wg.w + rb[3];
        float m = l0; int am = 0;
        if (l1 > m) { m = l1; am = 1; }
        if (l2 > m) { m = l2; am = 2; }
        if (l3 > m) { m = l3; am = 3; }
        float sum = expf(l0-m) + expf(l1-m) + expf(l2-m) + expf(l3-m);
        g_eid[row]  = am;
        g_gate[row] = 1.0f / sum;   // = max softmax prob
        atomicAdd(&g_counts[am], 1);
    }
}

__global__ void k_offsets() {
    int off = 0;
    for (int e = 0; e < E_NUM; e++) {
        g_padoff[e] = off;
        off += ((g_counts[e] + BM - 1) / BM) * BM;
    }
    g_padoff[E_NUM] = off;
}

__global__ void k_scatter() {
    int row = blockIdx.x * 256 + threadIdx.x;
    int e = g_eid[row];
    int slot = g_padoff[e] + atomicAdd(&g_cursor[e], 1);
    g_perm[slot] = row;
}

__device__ __forceinline__ int tile_expert(int m0) {
    int e = 0;
    while (e < E_NUM-1 && m0 >= g_padoff[e+1]) e++;
    return e;
}

// MoE GEMM1: h[slot,1024] = gelu(z[perm]@W1_e + b1_e)
__global__ void k_moe1(const float* __restrict__ eW1, const float* __restrict__ eb1) {
    int m0 = blockIdx.y * BM;
    if (m0 >= g_padoff[E_NUM]) return;
    GEMM_SMEM
    int e = tile_expert(m0);
    const float* W1 = eW1 + (size_t)e * 256 * 1024;
    float acc[TM][TN] = {};
    int n0 = blockIdx.x * BN;
    gemm_accum(acc, g_z, 256, 256, W1, 1024, m0, n0, g_perm, As, Bs);
    int trow = threadIdx.x >> 4, tcol = threadIdx.x & 15;
    #pragma unroll
    for (int i = 0; i < TM; i++)
        #pragma unroll
        for (int j = 0; j < TN; j++) {
            int slot = m0 + trow*TM + i;
            int col  = n0 + tcol*TN + j;
            g_h[(size_t)slot*1024 + col] = gelu_exact(acc[i][j] + eb1[e*1024 + col]);
        }
}

// MoE GEMM2: z_final[row] = z[row] + gate[row]*(h@W2_e + b2_e)
__global__ void k_moe2(const float* __restrict__ eW2, const float* __restrict__ eb2) {
    int m0 = blockIdx.y * BM;
    if (m0 >= g_padoff[E_NUM]) return;
    GEMM_SMEM
    int e = tile_expert(m0);
    const float* W2 = eW2 + (size_t)e * 1024 * 256;
    float acc[TM][TN] = {};
    int n0 = blockIdx.x * BN;
    gemm_accum(acc, g_h, 1024, 1024, W2, 256, m0, n0, nullptr, As, Bs);
    int trow = threadIdx.x >> 4, tcol = threadIdx.x & 15;
    #pragma unroll
    for (int i = 0; i < TM; i++) {
        int slot = m0 + trow*TM + i;
        int row = g_perm[slot];
        if (row < 0) continue;
        float gate = g_gate[row];
        #pragma unroll
        for (int j = 0; j < TN; j++) {
            int col = n0 + tcol*TN + j;
            g_zf[(size_t)row*256 + col] =
                g_z[(size_t)row*256 + col] + gate * (acc[i][j] + eb2[e*256 + col]);
        }
    }
}

// t_pre = z_final @ gd_W1 + gd_b1
__global__ void k_tpre(const float* __restrict__ W, const float* __restrict__ b) {
    GEMM_SMEM
    float acc[TM][TN] = {};
    int m0 = blockIdx.y * BM, n0 = blockIdx.x * BN;
    gemm_accum(acc, g_zf, 256, 256, W, 256, m0, n0, nullptr, As, Bs);
    int trow = threadIdx.x >> 4, tcol = threadIdx.x & 15;
    #pragma unroll
    for (int i = 0; i < TM; i++)
        #pragma unroll
        for (int j = 0; j < TN; j++) {
            int row = m0 + trow*TM + i, col = n0 + tcol*TN + j;
            g_tpre[(size_t)row*256 + col] = acc[i][j] + b[col];
        }
}

// LayerNorm + gelu (warp per row)
__global__ void k_ln(const float* __restrict__ g, const float* __restrict__ beta) {
    int warp = threadIdx.x >> 5, lane = threadIdx.x & 31;
    int row = blockIdx.x * 8 + warp;
    float v[8]; float s = 0.f;
    #pragma unroll
    for (int i = 0; i < 8; i++) {
        v[i] = g_tpre[(size_t)row*256 + lane + 32*i];
        s += v[i];
    }
    #pragma unroll
    for (int off = 16; off; off >>= 1) s += __shfl_xor_sync(0xffffffffu, s, off);
    float mean = s * (1.f/256.f);
    float s2 = 0.f;
    #pragma unroll
    for (int i = 0; i < 8; i++) { float d = v[i] - mean; s2 = fmaf(d, d, s2); }
    #pragma unroll
    for (int off = 16; off; off >>= 1) s2 += __shfl_xor_sync(0xffffffffu, s2, off);
    float rs = rsqrtf(s2 * (1.f/256.f) + 1e-5f);
    #pragma unroll
    for (int i = 0; i < 8; i++) {
        int k = lane + 32*i;
        float x = g[k] * (v[i] - mean) * rs + beta[k];
        g_t[(size_t)row*256 + k] = gelu_exact(x);
    }
}

// Big GEMM: preds = t @ gd_W2 + gd_b2; even cols -> mu, odd -> theta
__global__ void k_gd2(const float* __restrict__ W, const float* __restrict__ b2,
                      const float* __restrict__ lib, float* __restrict__ out) {
    GEMM_SMEM
    float acc[TM][TN] = {};
    int m0 = blockIdx.y * BM, n0 = blockIdx.x * BN;
    gemm_accum(acc, g_t, 256, 256, W, N_GD2, m0, n0, nullptr, As, Bs);
    int trow = threadIdx.x >> 4, tcol = threadIdx.x & 15;
    const size_t THETA_OFF = (size_t)B_ROWS * G_NUM;
    #pragma unroll
    for (int i = 0; i < TM; i++) {
        int row = m0 + trow*TM + i;
        float lb = lib[row];
        #pragma unroll
        for (int j = 0; j < TN; j++) {
            int col = n0 + tcol*TN + j;
            if (col < N_GD2) {
                float v  = acc[i][j] + b2[col];
                float sp = (v > 20.f) ? v : log1pf(expf(v));
                int gidx = col >> 1;
                if (col & 1)
                    out[THETA_OFF + (size_t)row*G_NUM + gidx] = sp + 1e-6f;
                else
                    out[(size_t)row*G_NUM + gidx] = sp * lb + 1e-6f;
            }
        }
    }
}

// align hidden: a1 = gelu(z_final @ ap_W1 + ap_b1)   [B,128]
__global__ void k_ap1(const float* __restrict__ W, const float* __restrict__ b) {
    GEMM_SMEM
    float acc[TM][TN] = {};
    int m0 = blockIdx.y * BM, n0 = blockIdx.x * BN;
    gemm_accum(acc, g_zf, 256, 256, W, 128, m0, n0, nullptr, As, Bs);
    int trow = threadIdx.x >> 4, tcol = threadIdx.x & 15;
    #pragma unroll
    for (int i = 0; i < TM; i++)
        #pragma unroll
        for (int j = 0; j < TN; j++) {
            int row = m0 + trow*TM + i, col = n0 + tcol*TN + j;
            g_a1[(size_t)row*128 + col] = gelu_exact(acc[i][j] + b[col]);
        }
}

// align out: a1 @ ap_W2 + ap_b2 -> out[ALIGN_OFF + row*30 + c]
__global__ void k_ap2(const float* __restrict__ W2, const float* __restrict__ b2,
                      float* __restrict__ out) {
    __shared__ float Ws[128*SCVI_];
    __shared__ float bs[SCVI_];
    for (int i = threadIdx.x; i < 128*SCVI_; i += 256) Ws[i] = W2[i];
    if (threadIdx.x < SCVI_) bs[threadIdx.x] = b2[threadIdx.x];
    __syncthreads();
    int warp = threadIdx.x >> 5, lane = threadIdx.x & 31;
    int row = blockIdx.x * 8 + warp;
    float a[4];
    #pragma unroll
    for (int i = 0; i < 4; i++) a[i] = g_a1[(size_t)row*128 + lane + 32*i];
    const size_t ALIGN_OFF = 2ull * B_ROWS * G_NUM + B_ROWS;
    for (int c = 0; c < SCVI_; c++) {
        float s = 0.f;
        #pragma unroll
        for (int i = 0; i < 4; i++) s = fmaf(a[i], Ws[(lane + 32*i)*SCVI_ + c], s);
        #pragma unroll
        for (int off = 16; off; off >>= 1) s += __shfl_down_sync(0xffffffffu, s, off);
        if (lane == 0) out[ALIGN_OFF + (size_t)row*SCVI_ + c] = s + bs[c];
    }
}

// func hidden: f1 = gelu(z_final @ fh_W1 + fh_b1)  [B,64]
__global__ void k_fh1(const float* __restrict__ W, const float* __restrict__ b) {
    GEMM_SMEM
    float acc[TM][TN] = {};
    int m0 = blockIdx.y * BM, n0 = blockIdx.x * BN;
    gemm_accum(acc, g_zf, 256, 256, W, 64, m0, n0, nullptr, As, Bs);
    int trow = threadIdx.x >> 4, tcol = threadIdx.x & 15;
    #pragma unroll
    for (int i = 0; i < TM; i++)
        #pragma unroll
        for (int j = 0; j < TN; j++) {
            int row = m0 + trow*TM + i, col = n0 + tcol*TN + j;
            if (col < 64)
                g_f1[(size_t)row*64 + col] = gelu_exact(acc[i][j] + b[col]);
        }
}

// func out: sigmoid(f1 @ fh_W2 + fh_b2) -> out[FUNC_OFF + row]
__global__ void k_fh2(const float* __restrict__ W2, const float* __restrict__ b2,
                      float* __restrict__ out) {
    int warp = threadIdx.x >> 5, lane = threadIdx.x & 31;
    int row = blockIdx.x * 8 + warp;
    float v = g_f1[(size_t)row*64 + lane] * W2[lane]
            + g_f1[(size_t)row*64 + lane + 32] * W2[lane + 32];
    #pragma unroll
    for (int off = 16; off; off >>= 1) v += __shfl_down_sync(0xffffffffu, v, off);
    if (lane == 0) {
        const size_t FUNC_OFF = 2ull * B_ROWS * G_NUM;
        out[FUNC_OFF + row] = 1.f / (1.f + expf(-(v + b2[0])));
    }
}

// ---------------- launch ----------------
extern "C" void kernel_launch(void* const* d_in, const int* in_sizes, int n_in,
                              void* d_out, int out_size) {
    const float* vis   = (const float*)d_in[0];
    const float* pos   = (const float*)d_in[1];
    const float* grad  = (const float*)d_in[2];
    const float* lib   = (const float*)d_in[3];
    const float* fB    = (const float*)d_in[4];
    const float* img_W = (const float*)d_in[5];
    const float* img_b = (const float*)d_in[6];
    const float* pos_W = (const float*)d_in[7];
    const float* pos_b = (const float*)d_in[8];
    const float* rW    = (const float*)d_in[9];
    const float* rb    = (const float*)d_in[10];
    const float* eW1   = (const float*)d_in[11];
    const float* eb1   = (const float*)d_in[12];
    const float* eW2   = (const float*)d_in[13];
    const float* eb2   = (const float*)d_in[14];
    const float* gdW1  = (const float*)d_in[15];
    const float* gdb1  = (const float*)d_in[16];
    const float* gdg   = (const float*)d_in[17];
    const float* gdbe  = (const float*)d_in[18];
    const float* gdW2  = (const float*)d_in[19];
    const float* gdb2  = (const float*)d_in[20];
    const float* apW1  = (const float*)d_in[21];
    const float* apb1  = (const float*)d_in[22];
    const float* apW2  = (const float*)d_in[23];
    const float* apb2  = (const float*)d_in[24];
    const float* fhW1  = (const float*)d_in[25];
    const float* fhb1  = (const float*)d_in[26];
    const float* fhW2  = (const float*)d_in[27];
    const float* fhb2  = (const float*)d_in[28];
    float* out = (float*)d_out;

    k_four   <<<B_ROWS/8, 256>>>(pos, fB);
    k_init   <<<(MAX_TILES*BM + 255)/256, 256>>>();
    k_gemm_z <<<dim3(2,128), NTHREADS>>>(vis, img_W, img_b, pos_W, pos_b);
    k_router <<<B_ROWS/8, 256>>>(grad, rW, rb);
    k_offsets<<<1,1>>>();
    k_scatter<<<B_ROWS/256, 256>>>();
    k_moe1   <<<dim3(8, MAX_TILES), NTHREADS>>>(eW1, eb1);
    k_moe2   <<<dim3(2, MAX_TILES), NTHREADS>>>(eW2, eb2);
    k_tpre   <<<dim3(2,128), NTHREADS>>>(gdW1, gdb1);
    k_ln     <<<B_ROWS/8, 256>>>(gdg, gdbe);
    k_gd2    <<<dim3((N_GD2 + BN - 1)/BN, 128), NTHREADS>>>(gdW2, gdb2, lib, out);
    k_ap1    <<<dim3(1,128), NTHREADS>>>(apW1, apb1);
    k_ap2    <<<B_ROWS/8, 256>>>(apW2, apb2, out);
    k_fh1    <<<dim3(1,128), NTHREADS>>>(fhW1, fhb1);
    k_fh2    <<<B_ROWS/8, 256>>>(fhW2, fhb2, out);
}

// round 3
// speedup vs baseline: 1.8585x; 1.8585x over previous
#include <cuda_runtime.h>
#include <cstdint>
#include <math.h>

// ---------------- problem dims ----------------
#define B_ROWS 16384
#define D_VIS  1024
#define D_H    256
#define E_NUM  4
#define G_NUM  5000
#define MAP_   128
#define SCVI_  30
#define N_GD2  (G_NUM*2)

// ---------------- tf32 GEMM tile config ----------------
#define BM 128
#define BN 128
#define BK 32
#define STAGES 3
#define NTHREADS 256
#define AS_STRIDE 36            // (32+4) floats: %32==4 -> conflict-free A frags
#define BS_STRIDE 136           // (128+8) floats: %32==8 -> conflict-free B frags
#define AS_SIZE (BM*AS_STRIDE)  // 4608 floats
#define BS_SIZE (BK*BS_STRIDE)  // 4352 floats
#define STAGE_FLOATS (AS_SIZE + BS_SIZE)          // 8960 floats
#define SMEM_BYTES (STAGES*STAGE_FLOATS*4)        // 107520 B
#define MAX_TILES 132

// ---------------- scratch ----------------
__device__ float g_four[(size_t)B_ROWS*2*MAP_];
__device__ float g_z   [(size_t)B_ROWS*D_H];
__device__ float g_zf  [(size_t)B_ROWS*D_H];
__device__ float g_tpre[(size_t)B_ROWS*D_H];
__device__ float g_t   [(size_t)B_ROWS*D_H];
__device__ float g_a1  [(size_t)B_ROWS*128];
__device__ float g_f1  [(size_t)B_ROWS*64];
__device__ float g_h   [(size_t)MAX_TILES*BM*1024];
__device__ int   g_eid [B_ROWS];
__device__ float g_gate[B_ROWS];
__device__ int   g_perm[MAX_TILES*BM];
__device__ int   g_counts[E_NUM];
__device__ int   g_cursor[E_NUM];
__device__ int   g_padoff[E_NUM+1];

// ---------------- helpers ----------------
__device__ __forceinline__ float gelu_exact(float x) {
    return 0.5f * x * (1.0f + erff(x * 0.70710678118654752440f));
}
__device__ __forceinline__ uint32_t f2tf(float f) {
    uint32_t o; asm("cvt.rna.tf32.f32 %0, %1;" : "=r"(o) : "f"(f)); return o;
}
__device__ __forceinline__ void mma8(float* c, const uint32_t* a, const uint32_t* b) {
    asm volatile("mma.sync.aligned.m16n8k8.row.col.f32.tf32.tf32.f32 "
        "{%0,%1,%2,%3}, {%4,%5,%6,%7}, {%8,%9}, {%0,%1,%2,%3};"
        : "+f"(c[0]), "+f"(c[1]), "+f"(c[2]), "+f"(c[3])
        : "r"(a[0]), "r"(a[1]), "r"(a[2]), "r"(a[3]), "r"(b[0]), "r"(b[1]));
}
__device__ __forceinline__ void cp_async16(float* dst_smem, const float* src, int src_bytes) {
    uint32_t d = (uint32_t)__cvta_generic_to_shared(dst_smem);
    asm volatile("cp.async.cg.shared.global [%0], [%1], 16, %2;\n"
                 :: "r"(d), "l"(src), "r"(src_bytes));
}
__device__ __forceinline__ void cp_commit() { asm volatile("cp.async.commit_group;\n"); }
template<int N> __device__ __forceinline__ void cp_wait() {
    asm volatile("cp.async.wait_group %0;\n" :: "n"(N));
}

// Load one 128x32 A tile (optionally gathered via perm; row<0 -> zeros) and
// one 32x128 B tile (column-guarded vs N) into a pipeline stage via cp.async.
__device__ __forceinline__ void issue_tile(
    float* stage,
    const float* __restrict__ A, int lda,
    const float* __restrict__ W, int N,
    int m0, int n0, int k0, const int* __restrict__ perm)
{
    float* As = stage;
    float* Bs = stage + AS_SIZE;
    const int tid = threadIdx.x;
    // A: row = tid/2, 16 floats starting at (tid&1)*16
    int ar = tid >> 1;
    int ac = (tid & 1) * 16;
    int rowg = perm ? perm[m0 + ar] : (m0 + ar);
    const float* srcA = A + (size_t)(rowg < 0 ? 0 : rowg) * lda + k0 + ac;
    int szA = (rowg >= 0) ? 16 : 0;
    #pragma unroll
    for (int i = 0; i < 4; i++)
        cp_async16(As + ar*AS_STRIDE + ac + i*4, srcA + i*4, szA);
    // B: row = tid/8, 16 floats starting at (tid&7)*16
    int br = tid >> 3;
    int bc = (tid & 7) * 16;
    const float* srcB = W + (size_t)(k0 + br) * N + n0 + bc;
    #pragma unroll
    for (int i = 0; i < 4; i++) {
        int col = n0 + bc + i*4;
        int bytes = (N - col) * 4;
        bytes = bytes < 0 ? 0 : (bytes > 16 ? 16 : bytes);
        cp_async16(Bs + br*BS_STRIDE + bc + i*4, bytes > 0 ? (srcB + i*4) : W, bytes);
    }
}

// Pipelined tf32 GEMM accumulate: acc += A[tile m0] @ W[:, n0..n0+127]
// acc layout: acc[mi][ni][0..3] per mma m16n8k8 C-fragment.
__device__ __forceinline__ void gemm_tf32(
    float acc[4][4][4],
    const float* __restrict__ A, int lda, int K,
    const float* __restrict__ W, int N,
    int m0, int n0, const int* __restrict__ perm, float* sm)
{
    const int KT = K >> 5;
    #pragma unroll
    for (int s = 0; s < STAGES-1; s++) {
        if (s < KT) issue_tile(sm + s*STAGE_FLOATS, A, lda, W, N, m0, n0, s*BK, perm);
        cp_commit();
    }
    const int warp = threadIdx.x >> 5, lane = threadIdx.x & 31;
    const int mw = (warp >> 2) * 64, nw = (warp & 3) * 32;
    const int g = lane >> 2, t4 = lane & 3;

    for (int kt = 0; kt < KT; kt++) {
        int pre = kt + STAGES - 1;
        if (pre < KT) issue_tile(sm + (pre%STAGES)*STAGE_FLOATS, A, lda, W, N, m0, n0, pre*BK, perm);
        cp_commit();
        cp_wait<STAGES-1>();
        __syncthreads();
        const float* As = sm + (kt%STAGES)*STAGE_FLOATS;
        const float* Bs = As + AS_SIZE;
        #pragma unroll
        for (int ks = 0; ks < BK/8; ks++) {
            const int k0s = ks * 8;
            uint32_t af[4][4], bf[4][2];
            #pragma unroll
            for (int mi = 0; mi < 4; mi++) {
                int r = mw + mi*16 + g;
                af[mi][0] = f2tf(As[(r  )*AS_STRIDE + k0s + t4    ]);
                af[mi][1] = f2tf(As[(r+8)*AS_STRIDE + k0s + t4    ]);
                af[mi][2] = f2tf(As[(r  )*AS_STRIDE + k0s + t4 + 4]);
                af[mi][3] = f2tf(As[(r+8)*AS_STRIDE + k0s + t4 + 4]);
            }
            #pragma unroll
            for (int ni = 0; ni < 4; ni++) {
                int c = nw + ni*8 + g;
                bf[ni][0] = f2tf(Bs[(k0s + t4    )*BS_STRIDE + c]);
                bf[ni][1] = f2tf(Bs[(k0s + t4 + 4)*BS_STRIDE + c]);
            }
            #pragma unroll
            for (int mi = 0; mi < 4; mi++)
                #pragma unroll
                for (int ni = 0; ni < 4; ni++)
                    mma8(acc[mi][ni], af[mi], bf[ni]);
        }
        __syncthreads();
    }
}

#define FRAG_IDX \
    const int warp = threadIdx.x >> 5, lane = threadIdx.x & 31; \
    const int mw = (warp >> 2) * 64, nw = (warp & 3) * 32; \
    const int g = lane >> 2, t4 = lane & 3;

// ---------------- stage kernels ----------------
__global__ void k_four(const float* __restrict__ pos, const float* __restrict__ fB) {
    int w = threadIdx.x >> 5, lane = threadIdx.x & 31;
    int row = blockIdx.x * 8 + w;
    float p0 = pos[row*3+0], p1 = pos[row*3+1], p2 = pos[row*3+2];
    #pragma unroll
    for (int i = 0; i < 4; i++) {
        int c = lane + 32*i;
        float xp = 6.283185307179586477f * (p0*fB[c] + p1*fB[MAP_+c] + p2*fB[2*MAP_+c]);
        float s, co;
        sincosf(xp, &s, &co);
        g_four[(size_t)row*256 + c]       = s;
        g_four[(size_t)row*256 + 128 + c] = co;
    }
}

// z = vis@img_W + img_b + gelu(four@pos_W + pos_b)
__global__ void __launch_bounds__(NTHREADS, 2)
k_gemm_z(const float* __restrict__ vis,
         const float* __restrict__ img_W, const float* __restrict__ img_b,
         const float* __restrict__ pos_W, const float* __restrict__ pos_b) {
    extern __shared__ float sm[];
    float acc[4][4][4] = {};
    int m0 = blockIdx.y * BM, n0 = blockIdx.x * BN;
    FRAG_IDX
    gemm_tf32(acc, g_four, 256, 256, pos_W, 256, m0, n0, nullptr, sm);
    #pragma unroll
    for (int mi = 0; mi < 4; mi++)
        #pragma unroll
        for (int ni = 0; ni < 4; ni++) {
            int c0 = n0 + nw + ni*8 + t4*2;
            acc[mi][ni][0] = gelu_exact(acc[mi][ni][0] + pos_b[c0]);
            acc[mi][ni][1] = gelu_exact(acc[mi][ni][1] + pos_b[c0+1]);
            acc[mi][ni][2] = gelu_exact(acc[mi][ni][2] + pos_b[c0]);
            acc[mi][ni][3] = gelu_exact(acc[mi][ni][3] + pos_b[c0+1]);
        }
    gemm_tf32(acc, vis, D_VIS, D_VIS, img_W, 256, m0, n0, nullptr, sm);
    #pragma unroll
    for (int mi = 0; mi < 4; mi++)
        #pragma unroll
        for (int ni = 0; ni < 4; ni++) {
            int r0 = m0 + mw + mi*16 + g, r1 = r0 + 8;
            int c0 = n0 + nw + ni*8 + t4*2, c1 = c0 + 1;
            g_z[(size_t)r0*256 + c0] = acc[mi][ni][0] + img_b[c0];
            g_z[(size_t)r0*256 + c1] = acc[mi][ni][1] + img_b[c1];
            g_z[(size_t)r1*256 + c0] = acc[mi][ni][2] + img_b[c0];
            g_z[(size_t)r1*256 + c1] = acc[mi][ni][3] + img_b[c1];
        }
}

__global__ void k_init() {
    int idx = blockIdx.x * blockDim.x + threadIdx.x;
    if (idx < MAX_TILES*BM) g_perm[idx] = -1;
    if (idx < E_NUM) { g_counts[idx] = 0; g_cursor[idx] = 0; }
}

__global__ void k_router(const float* __restrict__ grad,
                         const float* __restrict__ rW, const float* __restrict__ rb) {
    int w = threadIdx.x >> 5, lane = threadIdx.x & 31;
    int row = blockIdx.x * 8 + w;
    float4 s = make_float4(0.f,0.f,0.f,0.f);
    #pragma unroll
    for (int i = 0; i < 8; i++) {
        int k = lane + 32*i;
        float zv = g_z[(size_t)row*256 + k];
        float4 wv = *(const float4*)(rW + k*4);
        s.x = fmaf(zv, wv.x, s.x); s.y = fmaf(zv, wv.y, s.y);
        s.z = fmaf(zv, wv.z, s.z); s.w = fmaf(zv, wv.w, s.w);
    }
    #pragma unroll
    for (int off = 16; off; off >>= 1) {
        s.x += __shfl_down_sync(0xffffffffu, s.x, off);
        s.y += __shfl_down_sync(0xffffffffu, s.y, off);
        s.z += __shfl_down_sync(0xffffffffu, s.z, off);
        s.w += __shfl_down_sync(0xffffffffu, s.w, off);
    }
    if (lane == 0) {
        float gv = grad[row];
        float4 wg = *(const float4*)(rW + 256*4);
        float l0 = s.x + gv*wg.x + rb[0];
        float l1 = s.y + gv*wg.y + rb[1];
        float l2 = s.z + gv*wg.z + rb[2];
        float l3 = s.w + gv*wg.w + rb[3];
        float m = l0; int am = 0;
        if (l1 > m) { m = l1; am = 1; }
        if (l2 > m) { m = l2; am = 2; }
        if (l3 > m) { m = l3; am = 3; }
        float sum = expf(l0-m) + expf(l1-m) + expf(l2-m) + expf(l3-m);
        g_eid[row]  = am;
        g_gate[row] = 1.0f / sum;
        atomicAdd(&g_counts[am], 1);
    }
}

__global__ void k_offsets() {
    int off = 0;
    for (int e = 0; e < E_NUM; e++) {
        g_padoff[e] = off;
        off += ((g_counts[e] + BM - 1) / BM) * BM;
    }
    g_padoff[E_NUM] = off;
}

__global__ void k_scatter() {
    int row = blockIdx.x * 256 + threadIdx.x;
    int e = g_eid[row];
    int slot = g_padoff[e] + atomicAdd(&g_cursor[e], 1);
    g_perm[slot] = row;
}

__device__ __forceinline__ int tile_expert(int m0) {
    int e = 0;
    while (e < E_NUM-1 && m0 >= g_padoff[e+1]) e++;
    return e;
}

__global__ void __launch_bounds__(NTHREADS, 2)
k_moe1(const float* __restrict__ eW1, const float* __restrict__ eb1) {
    int m0 = blockIdx.y * BM;
    if (m0 >= g_padoff[E_NUM]) return;
    extern __shared__ float sm[];
    int e = tile_expert(m0);
    const float* W1 = eW1 + (size_t)e * 256 * 1024;
    float acc[4][4][4] = {};
    int n0 = blockIdx.x * BN;
    gemm_tf32(acc, g_z, 256, 256, W1, 1024, m0, n0, g_perm, sm);
    FRAG_IDX
    #pragma unroll
    for (int mi = 0; mi < 4; mi++)
        #pragma unroll
        for (int ni = 0; ni < 4; ni++) {
            int r0 = m0 + mw + mi*16 + g, r1 = r0 + 8;
            int c0 = n0 + nw + ni*8 + t4*2, c1 = c0 + 1;
            g_h[(size_t)r0*1024 + c0] = gelu_exact(acc[mi][ni][0] + eb1[e*1024 + c0]);
            g_h[(size_t)r0*1024 + c1] = gelu_exact(acc[mi][ni][1] + eb1[e*1024 + c1]);
            g_h[(size_t)r1*1024 + c0] = gelu_exact(acc[mi][ni][2] + eb1[e*1024 + c0]);
            g_h[(size_t)r1*1024 + c1] = gelu_exact(acc[mi][ni][3] + eb1[e*1024 + c1]);
        }
}

__global__ void __launch_bounds__(NTHREADS, 2)
k_moe2(const float* __restrict__ eW2, const float* __restrict__ eb2) {
    int m0 = blockIdx.y * BM;
    if (m0 >= g_padoff[E_NUM]) return;
    extern __shared__ float sm[];
    int e = tile_expert(m0);
    const float* W2 = eW2 + (size_t)e * 1024 * 256;
    float acc[4][4][4] = {};
    int n0 = blockIdx.x * BN;
    gemm_tf32(acc, g_h, 1024, 1024, W2, 256, m0, n0, nullptr, sm);
    FRAG_IDX
    #pragma unroll
    for (int mi = 0; mi < 4; mi++)
        #pragma unroll
        for (int ni = 0; ni < 4; ni++) {
            int s0 = m0 + mw + mi*16 + g, s1 = s0 + 8;
            int c0 = n0 + nw + ni*8 + t4*2, c1 = c0 + 1;
            int r0 = g_perm[s0], r1 = g_perm[s1];
            if (r0 >= 0) {
                float gate = g_gate[r0];
                g_zf[(size_t)r0*256 + c0] = g_z[(size_t)r0*256 + c0] + gate*(acc[mi][ni][0] + eb2[e*256 + c0]);
                g_zf[(size_t)r0*256 + c1] = g_z[(size_t)r0*256 + c1] + gate*(acc[mi][ni][1] + eb2[e*256 + c1]);
            }
            if (r1 >= 0) {
                float gate = g_gate[r1];
                g_zf[(size_t)r1*256 + c0] = g_z[(size_t)r1*256 + c0] + gate*(acc[mi][ni][2] + eb2[e*256 + c0]);
                g_zf[(size_t)r1*256 + c1] = g_z[(size_t)r1*256 + c1] + gate*(acc[mi][ni][3] + eb2[e*256 + c1]);
            }
        }
}

__global__ void __launch_bounds__(NTHREADS, 2)
k_tpre(const float* __restrict__ W, const float* __restrict__ b) {
    extern __shared__ float sm[];
    float acc[4][4][4] = {};
    int m0 = blockIdx.y * BM, n0 = blockIdx.x * BN;
    gemm_tf32(acc, g_zf, 256, 256, W, 256, m0, n0, nullptr, sm);
    FRAG_IDX
    #pragma unroll
    for (int mi = 0; mi < 4; mi++)
        #pragma unroll
        for (int ni = 0; ni < 4; ni++) {
            int r0 = m0 + mw + mi*16 + g, r1 = r0 + 8;
            int c0 = n0 + nw + ni*8 + t4*2, c1 = c0 + 1;
            g_tpre[(size_t)r0*256 + c0] = acc[mi][ni][0] + b[c0];
            g_tpre[(size_t)r0*256 + c1] = acc[mi][ni][1] + b[c1];
            g_tpre[(size_t)r1*256 + c0] = acc[mi][ni][2] + b[c0];
            g_tpre[(size_t)r1*256 + c1] = acc[mi][ni][3] + b[c1];
        }
}

__global__ void k_ln(const float* __restrict__ gam, const float* __restrict__ beta) {
    int w = threadIdx.x >> 5, lane = threadIdx.x & 31;
    int row = blockIdx.x * 8 + w;
    float v[8]; float s = 0.f;
    #pragma unroll
    for (int i = 0; i < 8; i++) {
        v[i] = g_tpre[(size_t)row*256 + lane + 32*i];
        s += v[i];
    }
    #pragma unroll
    for (int off = 16; off; off >>= 1) s += __shfl_xor_sync(0xffffffffu, s, off);
    float mean = s * (1.f/256.f);
    float s2 = 0.f;
    #pragma unroll
    for (int i = 0; i < 8; i++) { float d = v[i] - mean; s2 = fmaf(d, d, s2); }
    #pragma unroll
    for (int off = 16; off; off >>= 1) s2 += __shfl_xor_sync(0xffffffffu, s2, off);
    float rs = rsqrtf(s2 * (1.f/256.f) + 1e-5f);
    #pragma unroll
    for (int i = 0; i < 8; i++) {
        int k = lane + 32*i;
        g_t[(size_t)row*256 + k] = gelu_exact(gam[k] * (v[i] - mean) * rs + beta[k]);
    }
}

__device__ __forceinline__ void gd2_emit(float* __restrict__ out,
                                         const float* __restrict__ lib,
                                         const float* __restrict__ b2,
                                         int row, int col, float v) {
    if (col >= N_GD2) return;
    v += b2[col];
    float sp = (v > 20.f) ? v : log1pf(expf(v));
    int gi = col >> 1;
    if (col & 1) out[(size_t)B_ROWS*G_NUM + (size_t)row*G_NUM + gi] = sp + 1e-6f;
    else         out[(size_t)row*G_NUM + gi] = sp * lib[row] + 1e-6f;
}

__global__ void __launch_bounds__(NTHREADS, 2)
k_gd2(const float* __restrict__ W, const float* __restrict__ b2,
      const float* __restrict__ lib, float* __restrict__ out) {
    extern __shared__ float sm[];
    float acc[4][4][4] = {};
    int m0 = blockIdx.y * BM, n0 = blockIdx.x * BN;
    gemm_tf32(acc, g_t, 256, 256, W, N_GD2, m0, n0, nullptr, sm);
    FRAG_IDX
    #pragma unroll
    for (int mi = 0; mi < 4; mi++)
        #pragma unroll
        for (int ni = 0; ni < 4; ni++) {
            int r0 = m0 + mw + mi*16 + g, r1 = r0 + 8;
            int c0 = n0 + nw + ni*8 + t4*2, c1 = c0 + 1;
            gd2_emit(out, lib, b2, r0, c0, acc[mi][ni][0]);
            gd2_emit(out, lib, b2, r0, c1, acc[mi][ni][1]);
            gd2_emit(out, lib, b2, r1, c0, acc[mi][ni][2]);
            gd2_emit(out, lib, b2, r1, c1, acc[mi][ni][3]);
        }
}

__global__ void __launch_bounds__(NTHREADS, 2)
k_ap1(const float* __restrict__ W, const float* __restrict__ b) {
    extern __shared__ float sm[];
    float acc[4][4][4] = {};
    int m0 = blockIdx.y * BM, n0 = 0;
    gemm_tf32(acc, g_zf, 256, 256, W, 128, m0, n0, nullptr, sm);
    FRAG_IDX
    #pragma unroll
    for (int mi = 0; mi < 4; mi++)
        #pragma unroll
        for (int ni = 0; ni < 4; ni++) {
            int r0 = m0 + mw + mi*16 + g, r1 = r0 + 8;
            int c0 = nw + ni*8 + t4*2, c1 = c0 + 1;
            g_a1[(size_t)r0*128 + c0] = gelu_exact(acc[mi][ni][0] + b[c0]);
            g_a1[(size_t)r0*128 + c1] = gelu_exact(acc[mi][ni][1] + b[c1]);
            g_a1[(size_t)r1*128 + c0] = gelu_exact(acc[mi][ni][2] + b[c0]);
            g_a1[(size_t)r1*128 + c1] = gelu_exact(acc[mi][ni][3] + b[c1]);
        }
}

__global__ void k_ap2(const float* __restrict__ W2, const float* __restrict__ b2,
                      float* __restrict__ out) {
    __shared__ float Ws[128*SCVI_];
    __shared__ float bs[SCVI_];
    for (int i = threadIdx.x; i < 128*SCVI_; i += 256) Ws[i] = W2[i];
    if (threadIdx.x < SCVI_) bs[threadIdx.x] = b2[threadIdx.x];
    __syncthreads();
    int w = threadIdx.x >> 5, lane = threadIdx.x & 31;
    int row = blockIdx.x * 8 + w;
    float a[4];
    #pragma unroll
    for (int i = 0; i < 4; i++) a[i] = g_a1[(size_t)row*128 + lane + 32*i];
    const size_t ALIGN_OFF = 2ull * B_ROWS * G_NUM + B_ROWS;
    for (int c = 0; c < SCVI_; c++) {
        float s = 0.f;
        #pragma unroll
        for (int i = 0; i < 4; i++) s = fmaf(a[i], Ws[(lane + 32*i)*SCVI_ + c], s);
        #pragma unroll
        for (int off = 16; off; off >>= 1) s += __shfl_down_sync(0xffffffffu, s, off);
        if (lane == 0) out[ALIGN_OFF + (size_t)row*SCVI_ + c] = s + bs[c];
    }
}

__global__ void __launch_bounds__(NTHREADS, 2)
k_fh1(const float* __restrict__ W, const float* __restrict__ b) {
    extern __shared__ float sm[];
    float acc[4][4][4] = {};
    int m0 = blockIdx.y * BM, n0 = 0;
    gemm_tf32(acc, g_zf, 256, 256, W, 64, m0, n0, nullptr, sm);
    FRAG_IDX
    #pragma unroll
    for (int mi = 0; mi < 4; mi++)
        #pragma unroll
        for (int ni = 0; ni < 4; ni++) {
            int r0 = m0 + mw + mi*16 + g, r1 = r0 + 8;
            int c0 = nw + ni*8 + t4*2, c1 = c0 + 1;
            if (c0 < 64) {
                g_f1[(size_t)r0*64 + c0] = gelu_exact(acc[mi][ni][0] + b[c0]);
                g_f1[(size_t)r1*64 + c0] = gelu_exact(acc[mi][ni][2] + b[c0]);
            }
            if (c1 < 64) {
                g_f1[(size_t)r0*64 + c1] = gelu_exact(acc[mi][ni][1] + b[c1]);
                g_f1[(size_t)r1*64 + c1] = gelu_exact(acc[mi][ni][3] + b[c1]);
            }
        }
}

__global__ void k_fh2(const float* __restrict__ W2, const float* __restrict__ b2,
                      float* __restrict__ out) {
    int w = threadIdx.x >> 5, lane = threadIdx.x & 31;
    int row = blockIdx.x * 8 + w;
    float v = g_f1[(size_t)row*64 + lane] * W2[lane]
            + g_f1[(size_t)row*64 + lane + 32] * W2[lane + 32];
    #pragma unroll
    for (int off = 16; off; off >>= 1) v += __shfl_down_sync(0xffffffffu, v, off);
    if (lane == 0) {
        const size_t FUNC_OFF = 2ull * B_ROWS * G_NUM;
        out[FUNC_OFF + row] = 1.f / (1.f + expf(-(v + b2[0])));
    }
}

// ---------------- launch ----------------
extern "C" void kernel_launch(void* const* d_in, const int* in_sizes, int n_in,
                              void* d_out, int out_size) {
    const float* vis   = (const float*)d_in[0];
    const float* pos   = (const float*)d_in[1];
    const float* grad  = (const float*)d_in[2];
    const float* lib   = (const float*)d_in[3];
    const float* fB    = (const float*)d_in[4];
    const float* img_W = (const float*)d_in[5];
    const float* img_b = (const float*)d_in[6];
    const float* pos_W = (const float*)d_in[7];
    const float* pos_b = (const float*)d_in[8];
    const float* rW    = (const float*)d_in[9];
    const float* rb    = (const float*)d_in[10];
    const float* eW1   = (const float*)d_in[11];
    const float* eb1   = (const float*)d_in[12];
    const float* eW2   = (const float*)d_in[13];
    const float* eb2   = (const float*)d_in[14];
    const float* gdW1  = (const float*)d_in[15];
    const float* gdb1  = (const float*)d_in[16];
    const float* gdg   = (const float*)d_in[17];
    const float* gdbe  = (const float*)d_in[18];
    const float* gdW2  = (const float*)d_in[19];
    const float* gdb2  = (const float*)d_in[20];
    const float* apW1  = (const float*)d_in[21];
    const float* apb1  = (const float*)d_in[22];
    const float* apW2  = (const float*)d_in[23];
    const float* apb2  = (const float*)d_in[24];
    const float* fhW1  = (const float*)d_in[25];
    const float* fhb1  = (const float*)d_in[26];
    const float* fhW2  = (const float*)d_in[27];
    const float* fhb2  = (const float*)d_in[28];
    float* out = (float*)d_out;

    static const int SM = SMEM_BYTES;
    cudaFuncSetAttribute(k_gemm_z, cudaFuncAttributeMaxDynamicSharedMemorySize, SM);
    cudaFuncSetAttribute(k_moe1,   cudaFuncAttributeMaxDynamicSharedMemorySize, SM);
    cudaFuncSetAttribute(k_moe2,   cudaFuncAttributeMaxDynamicSharedMemorySize, SM);
    cudaFuncSetAttribute(k_tpre,   cudaFuncAttributeMaxDynamicSharedMemorySize, SM);
    cudaFuncSetAttribute(k_gd2,    cudaFuncAttributeMaxDynamicSharedMemorySize, SM);
    cudaFuncSetAttribute(k_ap1,    cudaFuncAttributeMaxDynamicSharedMemorySize, SM);
    cudaFuncSetAttribute(k_fh1,    cudaFuncAttributeMaxDynamicSharedMemorySize, SM);

    k_four   <<<B_ROWS/8, 256>>>(pos, fB);
    k_init   <<<(MAX_TILES*BM + 255)/256, 256>>>();
    k_gemm_z <<<dim3(2,128), NTHREADS, SM>>>(vis, img_W, img_b, pos_W, pos_b);
    k_router <<<B_ROWS/8, 256>>>(grad, rW, rb);
    k_offsets<<<1,1>>>();
    k_scatter<<<B_ROWS/256, 256>>>();
    k_moe1   <<<dim3(8, MAX_TILES), NTHREADS, SM>>>(eW1, eb1);
    k_moe2   <<<dim3(2, MAX_TILES), NTHREADS, SM>>>(eW2, eb2);
    k_tpre   <<<dim3(2,128), NTHREADS, SM>>>(gdW1, gdb1);
    k_ln     <<<B_ROWS/8, 256>>>(gdg, gdbe);
    k_gd2    <<<dim3((N_GD2 + BN - 1)/BN, 128), NTHREADS, SM>>>(gdW2, gdb2, lib, out);
    k_ap1    <<<dim3(1,128), NTHREADS, SM>>>(apW1, apb1);
    k_ap2    <<<B_ROWS/8, 256>>>(apW2, apb2, out);
    k_fh1    <<<dim3(1,128), NTHREADS, SM>>>(fhW1, fhb1);
    k_fh2    <<<B_ROWS/8, 256>>>(fhW2, fhb2, out);
}

// round 4
// speedup vs baseline: 1.8605x; 1.0011x over previous
#include <cuda_runtime.h>
#include <cstdint>
#include <math.h>

// ---------------- problem dims ----------------
#define B_ROWS 16384
#define D_VIS  1024
#define D_H    256
#define E_NUM  4
#define G_NUM  5000
#define MAP_   128
#define SCVI_  30
#define N_GD2  (G_NUM*2)

// ---------------- tf32 GEMM tile config ----------------
#define BM 128
#define BN 128
#define BK 32
#define STAGES 3
#define NTHREADS 256
#define AS_STRIDE 36            // (32+4) floats: %32==4 -> conflict-free A frags
#define BS_STRIDE 136           // (128+8) floats: %32==8 -> conflict-free B frags
#define AS_SIZE (BM*AS_STRIDE)  // 4608 floats
#define BS_SIZE (BK*BS_STRIDE)  // 4352 floats
#define STAGE_FLOATS (AS_SIZE + BS_SIZE)          // 8960 floats
#define SMEM_BYTES (STAGES*STAGE_FLOATS*4)        // 107520 B
#define MAX_TILES 132

// ---------------- scratch ----------------
__device__ float g_four[(size_t)B_ROWS*2*MAP_];
__device__ float g_z   [(size_t)B_ROWS*D_H];
__device__ float g_zf  [(size_t)B_ROWS*D_H];
__device__ float g_tpre[(size_t)B_ROWS*D_H];
__device__ float g_t   [(size_t)B_ROWS*D_H];
__device__ float g_a1  [(size_t)B_ROWS*128];
__device__ float g_f1  [(size_t)B_ROWS*64];
__device__ float g_h   [(size_t)MAX_TILES*BM*1024];
__device__ int   g_eid [B_ROWS];
__device__ float g_gate[B_ROWS];
__device__ int   g_perm[MAX_TILES*BM];
__device__ int   g_counts[E_NUM];
__device__ int   g_cursor[E_NUM];
__device__ int   g_padoff[E_NUM+1];

// ---------------- helpers ----------------
__device__ __forceinline__ float gelu_exact(float x) {
    return 0.5f * x * (1.0f + erff(x * 0.70710678118654752440f));
}
__device__ __forceinline__ uint32_t f2tf(float f) {
    uint32_t o; asm("cvt.rna.tf32.f32 %0, %1;" : "=r"(o) : "f"(f)); return o;
}
__device__ __forceinline__ void mma8(float* c, const uint32_t* a, const uint32_t* b) {
    asm volatile("mma.sync.aligned.m16n8k8.row.col.f32.tf32.tf32.f32 "
        "{%0,%1,%2,%3}, {%4,%5,%6,%7}, {%8,%9}, {%0,%1,%2,%3};"
        : "+f"(c[0]), "+f"(c[1]), "+f"(c[2]), "+f"(c[3])
        : "r"(a[0]), "r"(a[1]), "r"(a[2]), "r"(a[3]), "r"(b[0]), "r"(b[1]));
}
__device__ __forceinline__ void cp_async16(float* dst_smem, const float* src, int src_bytes) {
    uint32_t d = (uint32_t)__cvta_generic_to_shared(dst_smem);
    asm volatile("cp.async.cg.shared.global [%0], [%1], 16, %2;\n"
                 :: "r"(d), "l"(src), "r"(src_bytes));
}
__device__ __forceinline__ void cp_commit() { asm volatile("cp.async.commit_group;\n"); }
template<int N> __device__ __forceinline__ void cp_wait() {
    asm volatile("cp.async.wait_group %0;\n" :: "n"(N));
}

// Load one 128x32 A tile (optionally gathered via perm; row<0 -> zeros) and
// one 32x128 B tile (column-guarded vs N) into a pipeline stage via cp.async.
__device__ __forceinline__ void issue_tile(
    float* stage,
    const float* __restrict__ A, int lda,
    const float* __restrict__ W, int N,
    int m0, int n0, int k0, const int* __restrict__ perm)
{
    float* As = stage;
    float* Bs = stage + AS_SIZE;
    const int tid = threadIdx.x;
    // A: row = tid/2, 16 floats starting at (tid&1)*16
    int ar = tid >> 1;
    int ac = (tid & 1) * 16;
    int rowg = perm ? perm[m0 + ar] : (m0 + ar);
    const float* srcA = A + (size_t)(rowg < 0 ? 0 : rowg) * lda + k0 + ac;
    int szA = (rowg >= 0) ? 16 : 0;
    #pragma unroll
    for (int i = 0; i < 4; i++)
        cp_async16(As + ar*AS_STRIDE + ac + i*4, srcA + i*4, szA);
    // B: row = tid/8, 16 floats starting at (tid&7)*16
    int br = tid >> 3;
    int bc = (tid & 7) * 16;
    const float* srcB = W + (size_t)(k0 + br) * N + n0 + bc;
    #pragma unroll
    for (int i = 0; i < 4; i++) {
        int col = n0 + bc + i*4;
        int bytes = (N - col) * 4;
        bytes = bytes < 0 ? 0 : (bytes > 16 ? 16 : bytes);
        cp_async16(Bs + br*BS_STRIDE + bc + i*4, bytes > 0 ? (srcB + i*4) : W, bytes);
    }
}

// Pipelined tf32 GEMM accumulate: acc += A[tile m0] @ W[:, n0..n0+127]
// acc layout: acc[mi][ni][0..3] per mma m16n8k8 C-fragment.
__device__ __forceinline__ void gemm_tf32(
    float acc[4][4][4],
    const float* __restrict__ A, int lda, int K,
    const float* __restrict__ W, int N,
    int m0, int n0, const int* __restrict__ perm, float* sm)
{
    const int KT = K >> 5;
    #pragma unroll
    for (int s = 0; s < STAGES-1; s++) {
        if (s < KT) issue_tile(sm + s*STAGE_FLOATS, A, lda, W, N, m0, n0, s*BK, perm);
        cp_commit();
    }
    const int warp = threadIdx.x >> 5, lane = threadIdx.x & 31;
    const int mw = (warp >> 2) * 64, nw = (warp & 3) * 32;
    const int g = lane >> 2, t4 = lane & 3;

    for (int kt = 0; kt < KT; kt++) {
        int pre = kt + STAGES - 1;
        if (pre < KT) issue_tile(sm + (pre%STAGES)*STAGE_FLOATS, A, lda, W, N, m0, n0, pre*BK, perm);
        cp_commit();
        cp_wait<STAGES-1>();
        __syncthreads();
        const float* As = sm + (kt%STAGES)*STAGE_FLOATS;
        const float* Bs = As + AS_SIZE;
        #pragma unroll
        for (int ks = 0; ks < BK/8; ks++) {
            const int k0s = ks * 8;
            uint32_t af[4][4], bf[4][2];
            #pragma unroll
            for (int mi = 0; mi < 4; mi++) {
                int r = mw + mi*16 + g;
                af[mi][0] = f2tf(As[(r  )*AS_STRIDE + k0s + t4    ]);
                af[mi][1] = f2tf(As[(r+8)*AS_STRIDE + k0s + t4    ]);
                af[mi][2] = f2tf(As[(r  )*AS_STRIDE + k0s + t4 + 4]);
                af[mi][3] = f2tf(As[(r+8)*AS_STRIDE + k0s + t4 + 4]);
            }
            #pragma unroll
            for (int ni = 0; ni < 4; ni++) {
                int c = nw + ni*8 + g;
                bf[ni][0] = f2tf(Bs[(k0s + t4    )*BS_STRIDE + c]);
                bf[ni][1] = f2tf(Bs[(k0s + t4 + 4)*BS_STRIDE + c]);
            }
            #pragma unroll
            for (int mi = 0; mi < 4; mi++)
                #pragma unroll
                for (int ni = 0; ni < 4; ni++)
                    mma8(acc[mi][ni], af[mi], bf[ni]);
        }
        __syncthreads();
    }
}

#define FRAG_IDX \
    const int warp = threadIdx.x >> 5, lane = threadIdx.x & 31; \
    const int mw = (warp >> 2) * 64, nw = (warp & 3) * 32; \
    const int g = lane >> 2, t4 = lane & 3;

// ---------------- stage kernels ----------------
__global__ void k_four(const float* __restrict__ pos, const float* __restrict__ fB) {
    int w = threadIdx.x >> 5, lane = threadIdx.x & 31;
    int row = blockIdx.x * 8 + w;
    float p0 = pos[row*3+0], p1 = pos[row*3+1], p2 = pos[row*3+2];
    #pragma unroll
    for (int i = 0; i < 4; i++) {
        int c = lane + 32*i;
        float xp = 6.283185307179586477f * (p0*fB[c] + p1*fB[MAP_+c] + p2*fB[2*MAP_+c]);
        float s, co;
        sincosf(xp, &s, &co);
        g_four[(size_t)row*256 + c]       = s;
        g_four[(size_t)row*256 + 128 + c] = co;
    }
}

// z = vis@img_W + img_b + gelu(four@pos_W + pos_b)
__global__ void __launch_bounds__(NTHREADS, 2)
k_gemm_z(const float* __restrict__ vis,
         const float* __restrict__ img_W, const float* __restrict__ img_b,
         const float* __restrict__ pos_W, const float* __restrict__ pos_b) {
    extern __shared__ float sm[];
    float acc[4][4][4] = {};
    int m0 = blockIdx.y * BM, n0 = blockIdx.x * BN;
    FRAG_IDX
    gemm_tf32(acc, g_four, 256, 256, pos_W, 256, m0, n0, nullptr, sm);
    #pragma unroll
    for (int mi = 0; mi < 4; mi++)
        #pragma unroll
        for (int ni = 0; ni < 4; ni++) {
            int c0 = n0 + nw + ni*8 + t4*2;
            acc[mi][ni][0] = gelu_exact(acc[mi][ni][0] + pos_b[c0]);
            acc[mi][ni][1] = gelu_exact(acc[mi][ni][1] + pos_b[c0+1]);
            acc[mi][ni][2] = gelu_exact(acc[mi][ni][2] + pos_b[c0]);
            acc[mi][ni][3] = gelu_exact(acc[mi][ni][3] + pos_b[c0+1]);
        }
    gemm_tf32(acc, vis, D_VIS, D_VIS, img_W, 256, m0, n0, nullptr, sm);
    #pragma unroll
    for (int mi = 0; mi < 4; mi++)
        #pragma unroll
        for (int ni = 0; ni < 4; ni++) {
            int r0 = m0 + mw + mi*16 + g, r1 = r0 + 8;
            int c0 = n0 + nw + ni*8 + t4*2, c1 = c0 + 1;
            g_z[(size_t)r0*256 + c0] = acc[mi][ni][0] + img_b[c0];
            g_z[(size_t)r0*256 + c1] = acc[mi][ni][1] + img_b[c1];
            g_z[(size_t)r1*256 + c0] = acc[mi][ni][2] + img_b[c0];
            g_z[(size_t)r1*256 + c1] = acc[mi][ni][3] + img_b[c1];
        }
}

__global__ void k_init() {
    int idx = blockIdx.x * blockDim.x + threadIdx.x;
    if (idx < MAX_TILES*BM) g_perm[idx] = -1;
    if (idx < E_NUM) { g_counts[idx] = 0; g_cursor[idx] = 0; }
}

__global__ void k_router(const float* __restrict__ grad,
                         const float* __restrict__ rW, const float* __restrict__ rb) {
    int w = threadIdx.x >> 5, lane = threadIdx.x & 31;
    int row = blockIdx.x * 8 + w;
    float4 s = make_float4(0.f,0.f,0.f,0.f);
    #pragma unroll
    for (int i = 0; i < 8; i++) {
        int k = lane + 32*i;
        float zv = g_z[(size_t)row*256 + k];
        float4 wv = *(const float4*)(rW + k*4);
        s.x = fmaf(zv, wv.x, s.x); s.y = fmaf(zv, wv.y, s.y);
        s.z = fmaf(zv, wv.z, s.z); s.w = fmaf(zv, wv.w, s.w);
    }
    #pragma unroll
    for (int off = 16; off; off >>= 1) {
        s.x += __shfl_down_sync(0xffffffffu, s.x, off);
        s.y += __shfl_down_sync(0xffffffffu, s.y, off);
        s.z += __shfl_down_sync(0xffffffffu, s.z, off);
        s.w += __shfl_down_sync(0xffffffffu, s.w, off);
    }
    if (lane == 0) {
        float gv = grad[row];
        float4 wg = *(const float4*)(rW + 256*4);
        float l0 = s.x + gv*wg.x + rb[0];
        float l1 = s.y + gv*wg.y + rb[1];
        float l2 = s.z + gv*wg.z + rb[2];
        float l3 = s.w + gv*wg.w + rb[3];
        float m = l0; int am = 0;
        if (l1 > m) { m = l1; am = 1; }
        if (l2 > m) { m = l2; am = 2; }
        if (l3 > m) { m = l3; am = 3; }
        float sum = expf(l0-m) + expf(l1-m) + expf(l2-m) + expf(l3-m);
        g_eid[row]  = am;
        g_gate[row] = 1.0f / sum;
        atomicAdd(&g_counts[am], 1);
    }
}

__global__ void k_offsets() {
    int off = 0;
    for (int e = 0; e < E_NUM; e++) {
        g_padoff[e] = off;
        off += ((g_counts[e] + BM - 1) / BM) * BM;
    }
    g_padoff[E_NUM] = off;
}

__global__ void k_scatter() {
    int row = blockIdx.x * 256 + threadIdx.x;
    int e = g_eid[row];
    int slot = g_padoff[e] + atomicAdd(&g_cursor[e], 1);
    g_perm[slot] = row;
}

__device__ __forceinline__ int tile_expert(int m0) {
    int e = 0;
    while (e < E_NUM-1 && m0 >= g_padoff[e+1]) e++;
    return e;
}

__global__ void __launch_bounds__(NTHREADS, 2)
k_moe1(const float* __restrict__ eW1, const float* __restrict__ eb1) {
    int m0 = blockIdx.y * BM;
    if (m0 >= g_padoff[E_NUM]) return;
    extern __shared__ float sm[];
    int e = tile_expert(m0);
    const float* W1 = eW1 + (size_t)e * 256 * 1024;
    float acc[4][4][4] = {};
    int n0 = blockIdx.x * BN;
    gemm_tf32(acc, g_z, 256, 256, W1, 1024, m0, n0, g_perm, sm);
    FRAG_IDX
    #pragma unroll
    for (int mi = 0; mi < 4; mi++)
        #pragma unroll
        for (int ni = 0; ni < 4; ni++) {
            int r0 = m0 + mw + mi*16 + g, r1 = r0 + 8;
            int c0 = n0 + nw + ni*8 + t4*2, c1 = c0 + 1;
            g_h[(size_t)r0*1024 + c0] = gelu_exact(acc[mi][ni][0] + eb1[e*1024 + c0]);
            g_h[(size_t)r0*1024 + c1] = gelu_exact(acc[mi][ni][1] + eb1[e*1024 + c1]);
            g_h[(size_t)r1*1024 + c0] = gelu_exact(acc[mi][ni][2] + eb1[e*1024 + c0]);
            g_h[(size_t)r1*1024 + c1] = gelu_exact(acc[mi][ni][3] + eb1[e*1024 + c1]);
        }
}

__global__ void __launch_bounds__(NTHREADS, 2)
k_moe2(const float* __restrict__ eW2, const float* __restrict__ eb2) {
    int m0 = blockIdx.y * BM;
    if (m0 >= g_padoff[E_NUM]) return;
    extern __shared__ float sm[];
    int e = tile_expert(m0);
    const float* W2 = eW2 + (size_t)e * 1024 * 256;
    float acc[4][4][4] = {};
    int n0 = blockIdx.x * BN;
    gemm_tf32(acc, g_h, 1024, 1024, W2, 256, m0, n0, nullptr, sm);
    FRAG_IDX
    #pragma unroll
    for (int mi = 0; mi < 4; mi++)
        #pragma unroll
        for (int ni = 0; ni < 4; ni++) {
            int s0 = m0 + mw + mi*16 + g, s1 = s0 + 8;
            int c0 = n0 + nw + ni*8 + t4*2, c1 = c0 + 1;
            int r0 = g_perm[s0], r1 = g_perm[s1];
            if (r0 >= 0) {
                float gate = g_gate[r0];
                g_zf[(size_t)r0*256 + c0] = g_z[(size_t)r0*256 + c0] + gate*(acc[mi][ni][0] + eb2[e*256 + c0]);
                g_zf[(size_t)r0*256 + c1] = g_z[(size_t)r0*256 + c1] + gate*(acc[mi][ni][1] + eb2[e*256 + c1]);
            }
            if (r1 >= 0) {
                float gate = g_gate[r1];
                g_zf[(size_t)r1*256 + c0] = g_z[(size_t)r1*256 + c0] + gate*(acc[mi][ni][2] + eb2[e*256 + c0]);
                g_zf[(size_t)r1*256 + c1] = g_z[(size_t)r1*256 + c1] + gate*(acc[mi][ni][3] + eb2[e*256 + c1]);
            }
        }
}

__global__ void __launch_bounds__(NTHREADS, 2)
k_tpre(const float* __restrict__ W, const float* __restrict__ b) {
    extern __shared__ float sm[];
    float acc[4][4][4] = {};
    int m0 = blockIdx.y * BM, n0 = blockIdx.x * BN;
    gemm_tf32(acc, g_zf, 256, 256, W, 256, m0, n0, nullptr, sm);
    FRAG_IDX
    #pragma unroll
    for (int mi = 0; mi < 4; mi++)
        #pragma unroll
        for (int ni = 0; ni < 4; ni++) {
            int r0 = m0 + mw + mi*16 + g, r1 = r0 + 8;
            int c0 = n0 + nw + ni*8 + t4*2, c1 = c0 + 1;
            g_tpre[(size_t)r0*256 + c0] = acc[mi][ni][0] + b[c0];
            g_tpre[(size_t)r0*256 + c1] = acc[mi][ni][1] + b[c1];
            g_tpre[(size_t)r1*256 + c0] = acc[mi][ni][2] + b[c0];
            g_tpre[(size_t)r1*256 + c1] = acc[mi][ni][3] + b[c1];
        }
}

__global__ void k_ln(const float* __restrict__ gam, const float* __restrict__ beta) {
    int w = threadIdx.x >> 5, lane = threadIdx.x & 31;
    int row = blockIdx.x * 8 + w;
    float v[8]; float s = 0.f;
    #pragma unroll
    for (int i = 0; i < 8; i++) {
        v[i] = g_tpre[(size_t)row*256 + lane + 32*i];
        s += v[i];
    }
    #pragma unroll
    for (int off = 16; off; off >>= 1) s += __shfl_xor_sync(0xffffffffu, s, off);
    float mean = s * (1.f/256.f);
    float s2 = 0.f;
    #pragma unroll
    for (int i = 0; i < 8; i++) { float d = v[i] - mean; s2 = fmaf(d, d, s2); }
    #pragma unroll
    for (int off = 16; off; off >>= 1) s2 += __shfl_xor_sync(0xffffffffu, s2, off);
    float rs = rsqrtf(s2 * (1.f/256.f) + 1e-5f);
    #pragma unroll
    for (int i = 0; i < 8; i++) {
        int k = lane + 32*i;
        g_t[(size_t)row*256 + k] = gelu_exact(gam[k] * (v[i] - mean) * rs + beta[k]);
    }
}

__device__ __forceinline__ void gd2_emit(float* __restrict__ out,
                                         const float* __restrict__ lib,
                                         const float* __restrict__ b2,
                                         int row, int col, float v) {
    if (col >= N_GD2) return;
    v += b2[col];
    float sp = (v > 20.f) ? v : log1pf(expf(v));
    int gi = col >> 1;
    if (col & 1) out[(size_t)B_ROWS*G_NUM + (size_t)row*G_NUM + gi] = sp + 1e-6f;
    else         out[(size_t)row*G_NUM + gi] = sp * lib[row] + 1e-6f;
}

__global__ void __launch_bounds__(NTHREADS, 2)
k_gd2(const float* __restrict__ W, const float* __restrict__ b2,
      const float* __restrict__ lib, float* __restrict__ out) {
    extern __shared__ float sm[];
    float acc[4][4][4] = {};
    int m0 = blockIdx.y * BM, n0 = blockIdx.x * BN;
    gemm_tf32(acc, g_t, 256, 256, W, N_GD2, m0, n0, nullptr, sm);
    FRAG_IDX
    #pragma unroll
    for (int mi = 0; mi < 4; mi++)
        #pragma unroll
        for (int ni = 0; ni < 4; ni++) {
            int r0 = m0 + mw + mi*16 + g, r1 = r0 + 8;
            int c0 = n0 + nw + ni*8 + t4*2, c1 = c0 + 1;
            gd2_emit(out, lib, b2, r0, c0, acc[mi][ni][0]);
            gd2_emit(out, lib, b2, r0, c1, acc[mi][ni][1]);
            gd2_emit(out, lib, b2, r1, c0, acc[mi][ni][2]);
            gd2_emit(out, lib, b2, r1, c1, acc[mi][ni][3]);
        }
}

__global__ void __launch_bounds__(NTHREADS, 2)
k_ap1(const float* __restrict__ W, const float* __restrict__ b) {
    extern __shared__ float sm[];
    float acc[4][4][4] = {};
    int m0 = blockIdx.y * BM, n0 = 0;
    gemm_tf32(acc, g_zf, 256, 256, W, 128, m0, n0, nullptr, sm);
    FRAG_IDX
    #pragma unroll
    for (int mi = 0; mi < 4; mi++)
        #pragma unroll
        for (int ni = 0; ni < 4; ni++) {
            int r0 = m0 + mw + mi*16 + g, r1 = r0 + 8;
            int c0 = nw + ni*8 + t4*2, c1 = c0 + 1;
            g_a1[(size_t)r0*128 + c0] = gelu_exact(acc[mi][ni][0] + b[c0]);
            g_a1[(size_t)r0*128 + c1] = gelu_exact(acc[mi][ni][1] + b[c1]);
            g_a1[(size_t)r1*128 + c0] = gelu_exact(acc[mi][ni][2] + b[c0]);
            g_a1[(size_t)r1*128 + c1] = gelu_exact(acc[mi][ni][3] + b[c1]);
        }
}

__global__ void k_ap2(const float* __restrict__ W2, const float* __restrict__ b2,
                      float* __restrict__ out) {
    __shared__ float Ws[128*SCVI_];
    __shared__ float bs[SCVI_];
    for (int i = threadIdx.x; i < 128*SCVI_; i += 256) Ws[i] = W2[i];
    if (threadIdx.x < SCVI_) bs[threadIdx.x] = b2[threadIdx.x];
    __syncthreads();
    int w = threadIdx.x >> 5, lane = threadIdx.x & 31;
    int row = blockIdx.x * 8 + w;
    float a[4];
    #pragma unroll
    for (int i = 0; i < 4; i++) a[i] = g_a1[(size_t)row*128 + lane + 32*i];
    const size_t ALIGN_OFF = 2ull * B_ROWS * G_NUM + B_ROWS;
    for (int c = 0; c < SCVI_; c++) {
        float s = 0.f;
        #pragma unroll
        for (int i = 0; i < 4; i++) s = fmaf(a[i], Ws[(lane + 32*i)*SCVI_ + c], s);
        #pragma unroll
        for (int off = 16; off; off >>= 1) s += __shfl_down_sync(0xffffffffu, s, off);
        if (lane == 0) out[ALIGN_OFF + (size_t)row*SCVI_ + c] = s + bs[c];
    }
}

__global__ void __launch_bounds__(NTHREADS, 2)
k_fh1(const float* __restrict__ W, const float* __restrict__ b) {
    extern __shared__ float sm[];
    float acc[4][4][4] = {};
    int m0 = blockIdx.y * BM, n0 = 0;
    gemm_tf32(acc, g_zf, 256, 256, W, 64, m0, n0, nullptr, sm);
    FRAG_IDX
    #pragma unroll
    for (int mi = 0; mi < 4; mi++)
        #pragma unroll
        for (int ni = 0; ni < 4; ni++) {
            int r0 = m0 + mw + mi*16 + g, r1 = r0 + 8;
            int c0 = nw + ni*8 + t4*2, c1 = c0 + 1;
            if (c0 < 64) {
                g_f1[(size_t)r0*64 + c0] = gelu_exact(acc[mi][ni][0] + b[c0]);
                g_f1[(size_t)r1*64 + c0] = gelu_exact(acc[mi][ni][2] + b[c0]);
            }
            if (c1 < 64) {
                g_f1[(size_t)r0*64 + c1] = gelu_exact(acc[mi][ni][1] + b[c1]);
                g_f1[(size_t)r1*64 + c1] = gelu_exact(acc[mi][ni][3] + b[c1]);
            }
        }
}

__global__ void k_fh2(const float* __restrict__ W2, const float* __restrict__ b2,
                      float* __restrict__ out) {
    int w = threadIdx.x >> 5, lane = threadIdx.x & 31;
    int row = blockIdx.x * 8 + w;
    float v = g_f1[(size_t)row*64 + lane] * W2[lane]
            + g_f1[(size_t)row*64 + lane + 32] * W2[lane + 32];
    #pragma unroll
    for (int off = 16; off; off >>= 1) v += __shfl_down_sync(0xffffffffu, v, off);
    if (lane == 0) {
        const size_t FUNC_OFF = 2ull * B_ROWS * G_NUM;
        out[FUNC_OFF + row] = 1.f / (1.f + expf(-(v + b2[0])));
    }
}

// ---------------- launch ----------------
extern "C" void kernel_launch(void* const* d_in, const int* in_sizes, int n_in,
                              void* d_out, int out_size) {
    const float* vis   = (const float*)d_in[0];
    const float* pos   = (const float*)d_in[1];
    const float* grad  = (const float*)d_in[2];
    const float* lib   = (const float*)d_in[3];
    const float* fB    = (const float*)d_in[4];
    const float* img_W = (const float*)d_in[5];
    const float* img_b = (const float*)d_in[6];
    const float* pos_W = (const float*)d_in[7];
    const float* pos_b = (const float*)d_in[8];
    const float* rW    = (const float*)d_in[9];
    const float* rb    = (const float*)d_in[10];
    const float* eW1   = (const float*)d_in[11];
    const float* eb1   = (const float*)d_in[12];
    const float* eW2   = (const float*)d_in[13];
    const float* eb2   = (const float*)d_in[14];
    const float* gdW1  = (const float*)d_in[15];
    const float* gdb1  = (const float*)d_in[16];
    const float* gdg   = (const float*)d_in[17];
    const float* gdbe  = (const float*)d_in[18];
    const float* gdW2  = (const float*)d_in[19];
    const float* gdb2  = (const float*)d_in[20];
    const float* apW1  = (const float*)d_in[21];
    const float* apb1  = (const float*)d_in[22];
    const float* apW2  = (const float*)d_in[23];
    const float* apb2  = (const float*)d_in[24];
    const float* fhW1  = (const float*)d_in[25];
    const float* fhb1  = (const float*)d_in[26];
    const float* fhW2  = (const float*)d_in[27];
    const float* fhb2  = (const float*)d_in[28];
    float* out = (float*)d_out;

    static const int SM = SMEM_BYTES;
    cudaFuncSetAttribute(k_gemm_z, cudaFuncAttributeMaxDynamicSharedMemorySize, SM);
    cudaFuncSetAttribute(k_moe1,   cudaFuncAttributeMaxDynamicSharedMemorySize, SM);
    cudaFuncSetAttribute(k_moe2,   cudaFuncAttributeMaxDynamicSharedMemorySize, SM);
    cudaFuncSetAttribute(k_tpre,   cudaFuncAttributeMaxDynamicSharedMemorySize, SM);
    cudaFuncSetAttribute(k_gd2,    cudaFuncAttributeMaxDynamicSharedMemorySize, SM);
    cudaFuncSetAttribute(k_ap1,    cudaFuncAttributeMaxDynamicSharedMemorySize, SM);
    cudaFuncSetAttribute(k_fh1,    cudaFuncAttributeMaxDynamicSharedMemorySize, SM);

    k_four   <<<B_ROWS/8, 256>>>(pos, fB);
    k_init   <<<(MAX_TILES*BM + 255)/256, 256>>>();
    k_gemm_z <<<dim3(2,128), NTHREADS, SM>>>(vis, img_W, img_b, pos_W, pos_b);
    k_router <<<B_ROWS/8, 256>>>(grad, rW, rb);
    k_offsets<<<1,1>>>();
    k_scatter<<<B_ROWS/256, 256>>>();
    k_moe1   <<<dim3(8, MAX_TILES), NTHREADS, SM>>>(eW1, eb1);
    k_moe2   <<<dim3(2, MAX_TILES), NTHREADS, SM>>>(eW2, eb2);
    k_tpre   <<<dim3(2,128), NTHREADS, SM>>>(gdW1, gdb1);
    k_ln     <<<B_ROWS/8, 256>>>(gdg, gdbe);
    k_gd2    <<<dim3((N_GD2 + BN - 1)/BN, 128), NTHREADS, SM>>>(gdW2, gdb2, lib, out);
    k_ap1    <<<dim3(1,128), NTHREADS, SM>>>(apW1, apb1);
    k_ap2    <<<B_ROWS/8, 256>>>(apW2, apb2, out);
    k_fh1    <<<dim3(1,128), NTHREADS, SM>>>(fhW1, fhb1);
    k_fh2    <<<B_ROWS/8, 256>>>(fhW2, fhb2, out);
}